// round 8
// baseline (speedup 1.0000x reference)
#include <cuda_runtime.h>
#include <cuda_fp16.h>
#include <cstdint>

#define BB 64
#define EE 1024
#define NN_ 512
#define DD 64
#define HH 128
#define TT 5

// fp16-packed scratch (word = half2): edge_feature
__device__ uint32_t g_efh[BB * EE * (DD / 2)];   // 8 MB

// ---------------------------------------------------------------------------
// helpers
// ---------------------------------------------------------------------------
__device__ __forceinline__ uint32_t h2(float lo, float hi) {
    __half2 h = __floats2half2_rn(lo, hi);
    return *reinterpret_cast<uint32_t*>(&h);
}
__device__ __forceinline__ uint32_t sm_u32(const void* p) {
    return (uint32_t)__cvta_generic_to_shared(p);
}
__device__ __forceinline__ void ldsm4(uint32_t& r0, uint32_t& r1, uint32_t& r2,
                                      uint32_t& r3, uint32_t addr) {
    asm volatile("ldmatrix.sync.aligned.m8n8.x4.shared.b16 {%0,%1,%2,%3}, [%4];"
                 : "=r"(r0), "=r"(r1), "=r"(r2), "=r"(r3) : "r"(addr));
}
__device__ __forceinline__ void ldsm4t(uint32_t& r0, uint32_t& r1, uint32_t& r2,
                                       uint32_t& r3, uint32_t addr) {
    asm volatile("ldmatrix.sync.aligned.m8n8.x4.trans.shared.b16 {%0,%1,%2,%3}, [%4];"
                 : "=r"(r0), "=r"(r1), "=r"(r2), "=r"(r3) : "r"(addr));
}
__device__ __forceinline__ void mma16(float* c, uint32_t a0, uint32_t a1,
                                      uint32_t a2, uint32_t a3,
                                      uint32_t b0, uint32_t b1) {
    asm volatile(
        "mma.sync.aligned.m16n8k16.row.col.f32.f16.f16.f32 "
        "{%0,%1,%2,%3}, {%4,%5,%6,%7}, {%8,%9}, {%0,%1,%2,%3};"
        : "+f"(c[0]), "+f"(c[1]), "+f"(c[2]), "+f"(c[3])
        : "r"(a0), "r"(a1), "r"(a2), "r"(a3), "r"(b0), "r"(b1));
}

// ---------------------------------------------------------------------------
// KF: fused (edges = H @ ori) + per-type MLP mixture.
// A-frags: LDSM on [row][kpair]; B-frags: LDSM.trans on [k][n] halfs.
// All B staging is row-order (coalesced LDG, conflict-free STS).
// ---------------------------------------------------------------------------
#define XS_W    (128 * 36)
#define K1_AW   20
#define K1_ASZ  (128 * K1_AW)     // 2560 w
#define K1_BSZ  (32 * 36)         // ori tile [k=n 32][64 halfs, stride 72h]
#define K1_BUF  (K1_ASZ + K1_BSZ)
#define K2_W1_W (64 * 68)         // W1 [d][128 halfs, stride 136h]
#define K2_HS_W (128 * 68)        // Hs [e][hpair] (A-layout)
#define K2_W2_W (128 * 36)        // W2 [h][64 halfs, stride 72h]
#define K2_REGION_W (K2_W1_W + K2_HS_W + K2_W2_W + 640 + 256 + 128)
#define KF_REGION_W (K2_REGION_W > 2 * K1_BUF ? K2_REGION_W : 2 * K1_BUF)
#define KF_SMEM_BYTES ((XS_W + KF_REGION_W) * 4)

__global__ __launch_bounds__(256, 2) void kf_fused(
    const float* __restrict__ H,  const float* __restrict__ ori,
    const float* __restrict__ ed, const float* __restrict__ W1,
    const float* __restrict__ b1, const float* __restrict__ W2,
    const float* __restrict__ b2) {
    extern __shared__ uint32_t smw[];
    uint32_t* Xs     = smw;          // [128][36w] persistent
    uint32_t* region = smw + XS_W;

    const int b    = blockIdx.x >> 3;
    const int m0   = (blockIdx.x & 7) * 128;
    const size_t row0 = (size_t)blockIdx.x * 128;
    const int tid  = threadIdx.x;
    const int wid  = tid >> 5, lane = tid & 31;
    const int g = lane >> 2, t = lane & 3;
    const int l15 = lane & 15, lq = lane >> 4;
    const int j = lane >> 3;
    const int jrow = (j & 1) * 8 + (lane & 7);   // B trans-LDSM row (k)
    const int jcol = (j >> 1) * 8;               // B trans-LDSM col (n)
    const int wm = (wid >> 1) * 32, wn = (wid & 1) * 32;

    // ================= phase 1: edges tile = H[b] tile @ ori[b] =============
    {
        const float* Hb   = H   + (size_t)b * EE * NN_;
        const float* orib = ori + (size_t)b * NN_ * DD;

        float acc[2][4][4];
#pragma unroll
        for (int mi = 0; mi < 2; mi++)
#pragma unroll
            for (int ni = 0; ni < 4; ni++)
#pragma unroll
                for (int jj = 0; jj < 4; jj++) acc[mi][ni][jj] = 0.f;

        const uint32_t smP1 = sm_u32(region);
        const uint32_t offA  = ((wm + l15) * K1_AW + 4 * lq) * 4;
        const uint32_t offB1 = (uint32_t)(K1_ASZ * 4) +
                               (jrow * 72 + wn + jcol) * 2;

        float4 ra[4], rb[2];
#pragma unroll
        for (int p = 0; p < 4; p++) {
            int f = tid + p * 256;
            ra[p] = *(const float4*)(Hb + (size_t)(m0 + (f >> 3)) * NN_ + (f & 7) * 4);
        }
#pragma unroll
        for (int p = 0; p < 2; p++) {
            int f = tid + p * 256;
            rb[p] = *(const float4*)(orib + (size_t)(f >> 4) * DD + (f & 15) * 4);
        }
        {
            uint32_t* A0 = region; uint32_t* B0 = region + K1_ASZ;
#pragma unroll
            for (int p = 0; p < 4; p++) {
                int f = tid + p * 256;
                uint2 w; w.x = h2(ra[p].x, ra[p].y); w.y = h2(ra[p].z, ra[p].w);
                *(uint2*)&A0[(f >> 3) * K1_AW + (f & 7) * 2] = w;
            }
#pragma unroll
            for (int p = 0; p < 2; p++) {
                int f = tid + p * 256;
                uint2 w; w.x = h2(rb[p].x, rb[p].y); w.y = h2(rb[p].z, rb[p].w);
                *(uint2*)&B0[(f >> 4) * 36 + (f & 15) * 2] = w;
            }
        }
        __syncthreads();

        int buf = 0;
        for (int k0 = 0; k0 < NN_; k0 += 32) {
            const int kn = k0 + 32;
            if (kn < NN_) {
#pragma unroll
                for (int p = 0; p < 4; p++) {
                    int f = tid + p * 256;
                    ra[p] = *(const float4*)(Hb + (size_t)(m0 + (f >> 3)) * NN_ + kn + (f & 7) * 4);
                }
#pragma unroll
                for (int p = 0; p < 2; p++) {
                    int f = tid + p * 256;
                    rb[p] = *(const float4*)(orib + (size_t)(kn + (f >> 4)) * DD + (f & 15) * 4);
                }
            }
            const uint32_t base = smP1 + (uint32_t)(buf * (K1_BUF * 4));
#pragma unroll
            for (int kk = 0; kk < 2; kk++) {
                uint32_t a0[4], a1[4], bb0[4], bb1[4];
                ldsm4(a0[0], a0[1], a0[2], a0[3], base + offA + kk * 32);
                ldsm4(a1[0], a1[1], a1[2], a1[3], base + offA + 1280 + kk * 32);
                ldsm4t(bb0[0], bb0[1], bb0[2], bb0[3], base + offB1 + kk * 2304);
                ldsm4t(bb1[0], bb1[1], bb1[2], bb1[3], base + offB1 + kk * 2304 + 32);
                mma16(acc[0][0], a0[0], a0[1], a0[2], a0[3], bb0[0], bb0[1]);
                mma16(acc[0][1], a0[0], a0[1], a0[2], a0[3], bb0[2], bb0[3]);
                mma16(acc[0][2], a0[0], a0[1], a0[2], a0[3], bb1[0], bb1[1]);
                mma16(acc[0][3], a0[0], a0[1], a0[2], a0[3], bb1[2], bb1[3]);
                mma16(acc[1][0], a1[0], a1[1], a1[2], a1[3], bb0[0], bb0[1]);
                mma16(acc[1][1], a1[0], a1[1], a1[2], a1[3], bb0[2], bb0[3]);
                mma16(acc[1][2], a1[0], a1[1], a1[2], a1[3], bb1[0], bb1[1]);
                mma16(acc[1][3], a1[0], a1[1], a1[2], a1[3], bb1[2], bb1[3]);
            }
            if (kn < NN_) {
                uint32_t* An = region + (buf ^ 1) * K1_BUF;
                uint32_t* Bn = An + K1_ASZ;
#pragma unroll
                for (int p = 0; p < 4; p++) {
                    int f = tid + p * 256;
                    uint2 w; w.x = h2(ra[p].x, ra[p].y); w.y = h2(ra[p].z, ra[p].w);
                    *(uint2*)&An[(f >> 3) * K1_AW + (f & 7) * 2] = w;
                }
#pragma unroll
                for (int p = 0; p < 2; p++) {
                    int f = tid + p * 256;
                    uint2 w; w.x = h2(rb[p].x, rb[p].y); w.y = h2(rb[p].z, rb[p].w);
                    *(uint2*)&Bn[(f >> 4) * 36 + (f & 15) * 2] = w;
                }
            }
            __syncthreads();
            buf ^= 1;
        }

        // epilogue: pack acc -> Xs ([e][dpair], A-layout for GEMM1)
#pragma unroll
        for (int mi = 0; mi < 2; mi++)
#pragma unroll
            for (int ni = 0; ni < 4; ni++) {
                int r1 = wm + 16 * mi + g, r2 = r1 + 8;
                int cw = (wn >> 1) + 4 * ni + t;
                Xs[r1 * 36 + cw] = h2(acc[mi][ni][0], acc[mi][ni][1]);
                Xs[r2 * 36 + cw] = h2(acc[mi][ni][2], acc[mi][ni][3]);
            }
    }
    // ================= phase 2 setup ========================================
    uint32_t* W1s = region;               // [64 d][68w, stride 136 halfs]
    uint32_t* Hs  = W1s + K2_W1_W;        // [128 e][68w hpair]
    uint32_t* W2s = Hs + K2_HS_W;         // [128 h][36w, stride 72 halfs]
    float* wds = (float*)(W2s + K2_W2_W);
    float* b1s = wds + 640;
    float* b2s = b1s + 256;

    const int wn1 = (wid & 1) * 64;
    const int wn2 = (wid & 1) * 32;

    for (int f = tid; f < 640; f += 256) wds[f] = ed[row0 * TT + f];
#pragma unroll
    for (int p = 0; p < 8; p++) {
        int f = tid + p * 256;
        {   // W1 type 0: row d = f>>5, col h = (f&31)*4
            float4 v = *(const float4*)(W1 + (size_t)f * 4);
            uint2 w; w.x = h2(v.x, v.y); w.y = h2(v.z, v.w);
            *(uint2*)&W1s[(f >> 5) * 68 + (f & 31) * 2] = w;
        }
        {   // W2 type 0: row h = f>>4, col d = (f&15)*4
            float4 v = *(const float4*)(W2 + (size_t)f * 4);
            uint2 w; w.x = h2(v.x, v.y); w.y = h2(v.z, v.w);
            *(uint2*)&W2s[(f >> 4) * 36 + (f & 15) * 2] = w;
        }
    }
    if (tid < 128)      b1s[tid]       = b1[tid];
    else if (tid < 192) b2s[tid - 128] = b2[tid - 128];

    float Y[2][4][4];
#pragma unroll
    for (int mi = 0; mi < 2; mi++)
#pragma unroll
        for (int ni = 0; ni < 4; ni++)
#pragma unroll
            for (int jj = 0; jj < 4; jj++) Y[mi][ni][jj] = 0.f;

    const uint32_t smX  = sm_u32(Xs);
    const uint32_t smW1 = sm_u32(W1s);
    const uint32_t smH  = sm_u32(Hs);
    const uint32_t smW2 = sm_u32(W2s);
    const uint32_t offXA  = ((wm + l15) * 36 + 4 * lq) * 4;
    const uint32_t offHA  = ((wm + l15) * 68 + 4 * lq) * 4;
    const uint32_t offW1B = (jrow * 136 + wn1 + jcol) * 2;
    const uint32_t offW2B = (jrow * 72 + wn2 + jcol) * 2;

    __syncthreads();

    // ================= phase 2: 5-type MLP mixture ===========================
    for (int et = 0; et < TT; et++) {
        const int pb = et & 1;
        const int tn = (et + 1 < TT) ? et + 1 : et;

        // prefetch next W1 + biases (coalesced)
        float4 rW1[8];
#pragma unroll
        for (int p = 0; p < 8; p++)
            rW1[p] = *(const float4*)(W1 + (size_t)tn * DD * HH + (size_t)(tid + p * 256) * 4);
        float rb1v = 0.f, rb2v = 0.f;
        if (tid < 128)      rb1v = b1[tn * HH + tid];
        else if (tid < 192) rb2v = b2[tn * DD + (tid - 128)];

        // GEMM1: h = relu(X @ W1 + b1)  (128x128, k=64)
        float hacc[2][8][4];
#pragma unroll
        for (int mi = 0; mi < 2; mi++)
#pragma unroll
            for (int ni = 0; ni < 8; ni++)
#pragma unroll
                for (int jj = 0; jj < 4; jj++) hacc[mi][ni][jj] = 0.f;
#pragma unroll
        for (int kk = 0; kk < 4; kk++) {
            uint32_t a0[4], a1[4];
            ldsm4(a0[0], a0[1], a0[2], a0[3], smX + offXA + kk * 32);
            ldsm4(a1[0], a1[1], a1[2], a1[3], smX + offXA + 2304 + kk * 32);
#pragma unroll
            for (int nb = 0; nb < 4; nb++) {
                uint32_t bw[4];
                ldsm4t(bw[0], bw[1], bw[2], bw[3],
                       smW1 + offW1B + kk * 4352 + nb * 32);
                mma16(hacc[0][2 * nb],     a0[0], a0[1], a0[2], a0[3], bw[0], bw[1]);
                mma16(hacc[0][2 * nb + 1], a0[0], a0[1], a0[2], a0[3], bw[2], bw[3]);
                mma16(hacc[1][2 * nb],     a1[0], a1[1], a1[2], a1[3], bw[0], bw[1]);
                mma16(hacc[1][2 * nb + 1], a1[0], a1[1], a1[2], a1[3], bw[2], bw[3]);
            }
        }
        // bias + relu -> Hs
        const int wn1h = wn1 >> 1;
#pragma unroll
        for (int mi = 0; mi < 2; mi++) {
            int r1 = wm + 16 * mi + g, r2 = r1 + 8;
#pragma unroll
            for (int ni = 0; ni < 8; ni++) {
                int c = wn1 + 8 * ni + 2 * t;
                float bx = b1s[pb * 128 + c], by = b1s[pb * 128 + c + 1];
                Hs[r1 * 68 + wn1h + 4 * ni + t] =
                    h2(fmaxf(hacc[mi][ni][0] + bx, 0.f), fmaxf(hacc[mi][ni][1] + by, 0.f));
                Hs[r2 * 68 + wn1h + 4 * ni + t] =
                    h2(fmaxf(hacc[mi][ni][2] + bx, 0.f), fmaxf(hacc[mi][ni][3] + by, 0.f));
            }
        }
        __syncthreads();

        // commit prefetched W1(t+1)+biases; prefetch W2(t+1)
#pragma unroll
        for (int p = 0; p < 8; p++) {
            int f = tid + p * 256;
            uint2 w; w.x = h2(rW1[p].x, rW1[p].y); w.y = h2(rW1[p].z, rW1[p].w);
            *(uint2*)&W1s[(f >> 5) * 68 + (f & 31) * 2] = w;
        }
        if (tid < 128)      b1s[(pb ^ 1) * 128 + tid]        = rb1v;
        else if (tid < 192) b2s[(pb ^ 1) * 64 + (tid - 128)] = rb2v;
        float4 rW2[8];
#pragma unroll
        for (int p = 0; p < 8; p++)
            rW2[p] = *(const float4*)(W2 + (size_t)tn * HH * DD + (size_t)(tid + p * 256) * 4);

        // GEMM2: acc2 = h @ W2  (128x64, k=128)
        float acc2[2][4][4];
#pragma unroll
        for (int mi = 0; mi < 2; mi++)
#pragma unroll
            for (int ni = 0; ni < 4; ni++)
#pragma unroll
                for (int jj = 0; jj < 4; jj++) acc2[mi][ni][jj] = 0.f;
#pragma unroll
        for (int kk = 0; kk < 8; kk++) {
            uint32_t a0[4], a1[4];
            ldsm4(a0[0], a0[1], a0[2], a0[3], smH + offHA + kk * 32);
            ldsm4(a1[0], a1[1], a1[2], a1[3], smH + offHA + 4352 + kk * 32);
#pragma unroll
            for (int nb = 0; nb < 2; nb++) {
                uint32_t bw[4];
                ldsm4t(bw[0], bw[1], bw[2], bw[3],
                       smW2 + offW2B + kk * 2304 + nb * 32);
                mma16(acc2[0][2 * nb],     a0[0], a0[1], a0[2], a0[3], bw[0], bw[1]);
                mma16(acc2[0][2 * nb + 1], a0[0], a0[1], a0[2], a0[3], bw[2], bw[3]);
                mma16(acc2[1][2 * nb],     a1[0], a1[1], a1[2], a1[3], bw[0], bw[1]);
                mma16(acc2[1][2 * nb + 1], a1[0], a1[1], a1[2], a1[3], bw[2], bw[3]);
            }
        }
#pragma unroll
        for (int mi = 0; mi < 2; mi++) {
            int r1 = wm + 16 * mi + g, r2 = r1 + 8;
            float wA = wds[r1 * TT + et];
            float wB = wds[r2 * TT + et];
#pragma unroll
            for (int ni = 0; ni < 4; ni++) {
                int c = wn2 + 8 * ni + 2 * t;
                float bx = b2s[pb * 64 + c], by = b2s[pb * 64 + c + 1];
                Y[mi][ni][0] += wA * (acc2[mi][ni][0] + bx);
                Y[mi][ni][1] += wA * (acc2[mi][ni][1] + by);
                Y[mi][ni][2] += wB * (acc2[mi][ni][2] + bx);
                Y[mi][ni][3] += wB * (acc2[mi][ni][3] + by);
            }
        }
        __syncthreads();

        // commit prefetched W2(t+1)
#pragma unroll
        for (int p = 0; p < 8; p++) {
            int f = tid + p * 256;
            uint2 w; w.x = h2(rW2[p].x, rW2[p].y); w.y = h2(rW2[p].z, rW2[p].w);
            *(uint2*)&W2s[(f >> 4) * 36 + (f & 15) * 2] = w;
        }
    }

    // epilogue -> g_efh
    const int wn2h = wn2 >> 1;
#pragma unroll
    for (int mi = 0; mi < 2; mi++)
#pragma unroll
        for (int ni = 0; ni < 4; ni++) {
            int r1 = (int)row0 + wm + 16 * mi + g, r2 = r1 + 8;
            int cw = wn2h + 4 * ni + t;
            g_efh[(size_t)r1 * 32 + cw] = h2(Y[mi][ni][0], Y[mi][ni][1]);
            g_efh[(size_t)r2 * 32 + cw] = h2(Y[mi][ni][2], Y[mi][ni][3]);
        }
}

// ---------------------------------------------------------------------------
// K3: node_agg = H^T @ ef + concat ori. m-tile 64, e-chunk 64, 512 CTAs.
// Hp [e][n halfs] (A via trans-LDSM), Bs [e][d halfs] (B via trans-LDSM).
// Both staged in row order: coalesced LDG, raw uint4 copy for ef.
// ---------------------------------------------------------------------------
#define K3_HSZ (64 * 36)
#define K3_BSZ (64 * 36)
#define K3_BUF (K3_HSZ + K3_BSZ)
#define K3_SMEM_BYTES (2 * K3_BUF * 4)

__global__ __launch_bounds__(256) void k3_out(const float* __restrict__ H,
                                              const float* __restrict__ ori,
                                              float* __restrict__ out) {
    extern __shared__ uint32_t sw3[];

    const int b   = blockIdx.y;
    const int n0  = blockIdx.x * 64;
    const int tid = threadIdx.x;
    const int wid = tid >> 5, lane = tid & 31;
    const int g = lane >> 2, t = lane & 3;
    const int j = lane >> 3;
    const int wm = (wid >> 1) * 16, wn = (wid & 1) * 32;

    const float* Hb = H + (size_t)b * EE * NN_;
    const uint32_t* efb = g_efh + (size_t)b * EE * 32;

    float acc[4][4];
#pragma unroll
    for (int ni = 0; ni < 4; ni++)
#pragma unroll
        for (int jj = 0; jj < 4; jj++) acc[ni][jj] = 0.f;

    // trans-LDSM offsets (bytes)
    const uint32_t smHp = sm_u32(sw3);
    const uint32_t smBs = smHp + (uint32_t)(K3_HSZ * 4);
    const uint32_t offA3 = (((j >> 1) * 8 + (lane & 7)) * 72 + wm + (j & 1) * 8) * 2;
    const uint32_t offB3 = (((j & 1) * 8 + (lane & 7)) * 72 + wn + (j >> 1) * 8) * 2;

    float4 ha[4];
    uint4  ea[2];
#pragma unroll
    for (int p = 0; p < 4; p++) {
        int f = tid + p * 256;
        ha[p] = *(const float4*)(Hb + (size_t)(f >> 4) * NN_ + n0 + (f & 15) * 4);
    }
#pragma unroll
    for (int p = 0; p < 2; p++) {
        int f = tid + p * 256;
        ea[p] = *(const uint4*)&efb[(size_t)(f >> 3) * 32 + (f & 7) * 4];
    }
    {
        uint32_t* Hp = sw3; uint32_t* Bs = sw3 + K3_HSZ;
#pragma unroll
        for (int p = 0; p < 4; p++) {
            int f = tid + p * 256;
            uint2 w; w.x = h2(ha[p].x, ha[p].y); w.y = h2(ha[p].z, ha[p].w);
            *(uint2*)&Hp[(f >> 4) * 36 + (f & 15) * 2] = w;
        }
#pragma unroll
        for (int p = 0; p < 2; p++) {
            int f = tid + p * 256;
            *(uint4*)&Bs[(f >> 3) * 36 + (f & 7) * 4] = ea[p];
        }
    }
    __syncthreads();

    int buf = 0;
    for (int e0 = 0; e0 < EE; e0 += 64) {
        const int en = e0 + 64;
        if (en < EE) {
#pragma unroll
            for (int p = 0; p < 4; p++) {
                int f = tid + p * 256;
                ha[p] = *(const float4*)(Hb + (size_t)(en + (f >> 4)) * NN_ + n0 + (f & 15) * 4);
            }
#pragma unroll
            for (int p = 0; p < 2; p++) {
                int f = tid + p * 256;
                ea[p] = *(const uint4*)&efb[(size_t)(en + (f >> 3)) * 32 + (f & 7) * 4];
            }
        }
        const uint32_t hbase = smHp + (uint32_t)(buf * (K3_BUF * 4));
        const uint32_t bbase = smBs + (uint32_t)(buf * (K3_BUF * 4));
#pragma unroll
        for (int kk = 0; kk < 4; kk++) {
            uint32_t a[4], bb0[4], bb1[4];
            ldsm4t(a[0], a[1], a[2], a[3], hbase + offA3 + kk * 2304);
            ldsm4t(bb0[0], bb0[1], bb0[2], bb0[3], bbase + offB3 + kk * 2304);
            ldsm4t(bb1[0], bb1[1], bb1[2], bb1[3], bbase + offB3 + kk * 2304 + 32);
            mma16(acc[0], a[0], a[1], a[2], a[3], bb0[0], bb0[1]);
            mma16(acc[1], a[0], a[1], a[2], a[3], bb0[2], bb0[3]);
            mma16(acc[2], a[0], a[1], a[2], a[3], bb1[0], bb1[1]);
            mma16(acc[3], a[0], a[1], a[2], a[3], bb1[2], bb1[3]);
        }
        if (en < EE) {
            uint32_t* Hn = sw3 + (buf ^ 1) * K3_BUF;
            uint32_t* Bn = Hn + K3_HSZ;
#pragma unroll
            for (int p = 0; p < 4; p++) {
                int f = tid + p * 256;
                uint2 w; w.x = h2(ha[p].x, ha[p].y); w.y = h2(ha[p].z, ha[p].w);
                *(uint2*)&Hn[(f >> 4) * 36 + (f & 15) * 2] = w;
            }
#pragma unroll
            for (int p = 0; p < 2; p++) {
                int f = tid + p * 256;
                *(uint4*)&Bn[(f >> 3) * 36 + (f & 7) * 4] = ea[p];
            }
        }
        __syncthreads();
        buf ^= 1;
    }

    float*       outb = out + (size_t)b * NN_ * (2 * DD);
    const float* orib = ori + (size_t)b * NN_ * DD;
#pragma unroll
    for (int ni = 0; ni < 4; ni++) {
        int r1 = n0 + wm + g, r2 = r1 + 8;
        int c  = wn + 8 * ni + 2 * t;
        *(float2*)(outb + (size_t)r1 * (2 * DD) + c) =
            make_float2(acc[ni][0], acc[ni][1]);
        *(float2*)(outb + (size_t)r2 * (2 * DD) + c) =
            make_float2(acc[ni][2], acc[ni][3]);
    }
#pragma unroll
    for (int p = 0; p < 4; p++) {
        int f = tid + p * 256;
        int r = f >> 4, cq = f & 15;
        float4 v = *(const float4*)(orib + (size_t)(n0 + r) * DD + cq * 4);
        *(float4*)(outb + (size_t)(n0 + r) * (2 * DD) + DD + cq * 4) = v;
    }
}

// ---------------------------------------------------------------------------
extern "C" void kernel_launch(void* const* d_in, const int* in_sizes, int n_in,
                              void* d_out, int out_size) {
    const float* ed  = (const float*)d_in[0];
    const float* H   = (const float*)d_in[1];
    const float* ori = (const float*)d_in[2];
    const float* W1  = (const float*)d_in[3];
    const float* b1  = (const float*)d_in[4];
    const float* W2  = (const float*)d_in[5];
    const float* b2  = (const float*)d_in[6];
    float* out = (float*)d_out;

    cudaFuncSetAttribute(kf_fused, cudaFuncAttributeMaxDynamicSharedMemorySize,
                         KF_SMEM_BYTES);

    kf_fused<<<(BB * EE) / 128, 256, KF_SMEM_BYTES>>>(H, ori, ed, W1, b1, W2, b2);

    dim3 g3(NN_ / 64, BB);
    k3_out<<<g3, 256, K3_SMEM_BYTES>>>(H, ori, out);
}

// round 9
// speedup vs baseline: 1.1521x; 1.1521x over previous
#include <cuda_runtime.h>
#include <cuda_fp16.h>
#include <cstdint>

#define BB 64
#define EE 1024
#define NN_ 512
#define DD 64
#define HH 128
#define TT 5

// fp16-packed scratch (word = half2): edge_feature
__device__ uint32_t g_efh[BB * EE * (DD / 2)];   // 8 MB

// ---------------------------------------------------------------------------
// helpers
// ---------------------------------------------------------------------------
__device__ __forceinline__ uint32_t h2(float lo, float hi) {
    __half2 h = __floats2half2_rn(lo, hi);
    return *reinterpret_cast<uint32_t*>(&h);
}
__device__ __forceinline__ uint32_t sm_u32(const void* p) {
    return (uint32_t)__cvta_generic_to_shared(p);
}
__device__ __forceinline__ void ldsm4(uint32_t& r0, uint32_t& r1, uint32_t& r2,
                                      uint32_t& r3, uint32_t addr) {
    asm volatile("ldmatrix.sync.aligned.m8n8.x4.shared.b16 {%0,%1,%2,%3}, [%4];"
                 : "=r"(r0), "=r"(r1), "=r"(r2), "=r"(r3) : "r"(addr));
}
__device__ __forceinline__ void mma16(float* c, uint32_t a0, uint32_t a1,
                                      uint32_t a2, uint32_t a3,
                                      uint32_t b0, uint32_t b1) {
    asm volatile(
        "mma.sync.aligned.m16n8k16.row.col.f32.f16.f16.f32 "
        "{%0,%1,%2,%3}, {%4,%5,%6,%7}, {%8,%9}, {%0,%1,%2,%3};"
        : "+f"(c[0]), "+f"(c[1]), "+f"(c[2]), "+f"(c[3])
        : "r"(a0), "r"(a1), "r"(a2), "r"(a3), "r"(b0), "r"(b1));
}

// ---------------------------------------------------------------------------
// KF: fused (edges = H @ ori) + per-type MLP mixture.
// Phase 1: round-7 proven (A via LDSM, B scalar frags, coalesced staging).
// Phase 2: 8-way M-split warps; GEMM1 accum -> relu -> GEMM2 A-frags in regs
//          (no Hs smem round trip, 1 sync per type, parity weight buffers).
// ---------------------------------------------------------------------------
#define XS_W    (128 * 36)
#define K1_AW 20
#define K1_BW 72
#define K1_ASZ (128 * K1_AW)
#define K1_BSZ (16 * K1_BW)
#define K1_BUF (K1_ASZ + K1_BSZ)
#define W1_PW   (32 * 136)       // one parity: [32 kp(d)][136w n(h)]
#define W2_PW   (64 * 72)        // one parity: [64 kp(h)][72w n(d)]
#define K2_REGION_W (2 * W1_PW + 2 * W2_PW + 640 + 256 + 128)
#define KF_REGION_W (K2_REGION_W > 2 * K1_BUF ? K2_REGION_W : 2 * K1_BUF)
#define KF_SMEM_BYTES ((XS_W + KF_REGION_W) * 4)

__device__ __forceinline__ void stage_w(
    const float* __restrict__ W1, const float* __restrict__ W2,
    const float* __restrict__ b1, const float* __restrict__ b2,
    int tt, int par, uint32_t* W1s, uint32_t* W2s,
    float* b1s, float* b2s, int tid) {
    const float* w1 = W1 + (size_t)tt * DD * HH;
    const float* w2 = W2 + (size_t)tt * HH * DD;
#pragma unroll
    for (int p = 0; p < 4; p++) {
        int s = tid + p * 256;
        {   // W1 [64][128] -> kpair-packed [32][136w]
            int r = s >> 5, cq = s & 31;
            float4 f0 = *(const float4*)(w1 + (size_t)(2 * r) * HH + cq * 4);
            float4 f1 = *(const float4*)(w1 + (size_t)(2 * r + 1) * HH + cq * 4);
            uint4 w;
            w.x = h2(f0.x, f1.x); w.y = h2(f0.y, f1.y);
            w.z = h2(f0.z, f1.z); w.w = h2(f0.w, f1.w);
            *(uint4*)&W1s[par * W1_PW + r * 136 + cq * 4] = w;
        }
        {   // W2 [128][64] -> kpair-packed [64][72w]
            int r = s >> 4, cq = s & 15;
            float4 f0 = *(const float4*)(w2 + (size_t)(2 * r) * DD + cq * 4);
            float4 f1 = *(const float4*)(w2 + (size_t)(2 * r + 1) * DD + cq * 4);
            uint4 w;
            w.x = h2(f0.x, f1.x); w.y = h2(f0.y, f1.y);
            w.z = h2(f0.z, f1.z); w.w = h2(f0.w, f1.w);
            *(uint4*)&W2s[par * W2_PW + r * 72 + cq * 4] = w;
        }
    }
    if (tid < 128)      b1s[par * 128 + tid]        = b1[tt * HH + tid];
    else if (tid < 192) b2s[par * 64 + (tid - 128)] = b2[tt * DD + (tid - 128)];
}

__global__ __launch_bounds__(256, 2) void kf_fused(
    const float* __restrict__ H,  const float* __restrict__ ori,
    const float* __restrict__ ed, const float* __restrict__ W1,
    const float* __restrict__ b1, const float* __restrict__ W2,
    const float* __restrict__ b2) {
    extern __shared__ uint32_t smw[];
    uint32_t* Xs     = smw;          // [128][36w] persistent
    uint32_t* region = smw + XS_W;

    const int b    = blockIdx.x >> 3;
    const int m0   = (blockIdx.x & 7) * 128;
    const size_t row0 = (size_t)blockIdx.x * 128;
    const int tid  = threadIdx.x;
    const int wid  = tid >> 5, lane = tid & 31;
    const int g = lane >> 2, t = lane & 3;
    const int l15 = lane & 15, lq = lane >> 4;
    const int wm1 = (wid >> 1) * 32, wn1 = (wid & 1) * 32;   // phase-1 split

    // ================= phase 1: edges tile = H[b] tile @ ori[b] =============
    {
        const float* Hb   = H   + (size_t)b * EE * NN_;
        const float* orib = ori + (size_t)b * NN_ * DD;

        float acc[2][4][4];
#pragma unroll
        for (int mi = 0; mi < 2; mi++)
#pragma unroll
            for (int ni = 0; ni < 4; ni++)
#pragma unroll
                for (int jj = 0; jj < 4; jj++) acc[mi][ni][jj] = 0.f;

        const int br = tid >> 4, bcq = tid & 15;   // coalesced B staging

        const uint32_t smP1 = sm_u32(region);
        const uint32_t offA = ((wm1 + l15) * K1_AW + 4 * lq) * 4;

        float4 ra[4], rb0, rb1;
#pragma unroll
        for (int p = 0; p < 4; p++) {
            int f = tid + p * 256;
            ra[p] = *(const float4*)(Hb + (size_t)(m0 + (f >> 3)) * NN_ + (f & 7) * 4);
        }
        rb0 = *(const float4*)(orib + (size_t)(2 * br) * DD + bcq * 4);
        rb1 = *(const float4*)(orib + (size_t)(2 * br + 1) * DD + bcq * 4);
        {
            uint32_t* A0 = region; uint32_t* B0 = region + K1_ASZ;
#pragma unroll
            for (int p = 0; p < 4; p++) {
                int f = tid + p * 256;
                uint2 w; w.x = h2(ra[p].x, ra[p].y); w.y = h2(ra[p].z, ra[p].w);
                *(uint2*)&A0[(f >> 3) * K1_AW + (f & 7) * 2] = w;
            }
            uint4 w;
            w.x = h2(rb0.x, rb1.x); w.y = h2(rb0.y, rb1.y);
            w.z = h2(rb0.z, rb1.z); w.w = h2(rb0.w, rb1.w);
            *(uint4*)&B0[br * K1_BW + bcq * 4] = w;
        }
        __syncthreads();

        int buf = 0;
        for (int k0 = 0; k0 < NN_; k0 += 32) {
            const int kn = k0 + 32;
            if (kn < NN_) {
#pragma unroll
                for (int p = 0; p < 4; p++) {
                    int f = tid + p * 256;
                    ra[p] = *(const float4*)(Hb + (size_t)(m0 + (f >> 3)) * NN_ + kn + (f & 7) * 4);
                }
                rb0 = *(const float4*)(orib + (size_t)(kn + 2 * br) * DD + bcq * 4);
                rb1 = *(const float4*)(orib + (size_t)(kn + 2 * br + 1) * DD + bcq * 4);
            }
            const uint32_t abase = smP1 + (uint32_t)(buf * (K1_BUF * 4));
            const uint32_t* B_ = region + buf * K1_BUF + K1_ASZ;
#pragma unroll
            for (int kk = 0; kk < 2; kk++) {
                uint32_t a0[4], a1[4], bf[4][2];
                ldsm4(a0[0], a0[1], a0[2], a0[3], abase + offA + kk * 32);
                ldsm4(a1[0], a1[1], a1[2], a1[3], abase + offA + 1280 + kk * 32);
#pragma unroll
                for (int ni = 0; ni < 4; ni++) {
                    bf[ni][0] = B_[(8 * kk + t) * K1_BW + wn1 + 8 * ni + g];
                    bf[ni][1] = B_[(8 * kk + t + 4) * K1_BW + wn1 + 8 * ni + g];
                }
#pragma unroll
                for (int ni = 0; ni < 4; ni++) {
                    mma16(acc[0][ni], a0[0], a0[1], a0[2], a0[3], bf[ni][0], bf[ni][1]);
                    mma16(acc[1][ni], a1[0], a1[1], a1[2], a1[3], bf[ni][0], bf[ni][1]);
                }
            }
            if (kn < NN_) {
                uint32_t* An = region + (buf ^ 1) * K1_BUF;
                uint32_t* Bn = An + K1_ASZ;
#pragma unroll
                for (int p = 0; p < 4; p++) {
                    int f = tid + p * 256;
                    uint2 w; w.x = h2(ra[p].x, ra[p].y); w.y = h2(ra[p].z, ra[p].w);
                    *(uint2*)&An[(f >> 3) * K1_AW + (f & 7) * 2] = w;
                }
                uint4 w;
                w.x = h2(rb0.x, rb1.x); w.y = h2(rb0.y, rb1.y);
                w.z = h2(rb0.z, rb1.z); w.w = h2(rb0.w, rb1.w);
                *(uint4*)&Bn[br * K1_BW + bcq * 4] = w;
            }
            __syncthreads();
            buf ^= 1;
        }

        // epilogue: pack acc -> Xs ([e][dpair], A-layout for GEMM1)
#pragma unroll
        for (int mi = 0; mi < 2; mi++)
#pragma unroll
            for (int ni = 0; ni < 4; ni++) {
                int r1 = wm1 + 16 * mi + g, r2 = r1 + 8;
                int cw = (wn1 >> 1) + 4 * ni + t;
                Xs[r1 * 36 + cw] = h2(acc[mi][ni][0], acc[mi][ni][1]);
                Xs[r2 * 36 + cw] = h2(acc[mi][ni][2], acc[mi][ni][3]);
            }
    }
    // ================= phase 2 setup ========================================
    uint32_t* W1s = region;                    // 2 parity x [32][136w]
    uint32_t* W2s = region + 2 * W1_PW;        // 2 parity x [64][72w]
    float* wds = (float*)(W2s + 2 * W2_PW);    // [128][5]
    float* b1s = wds + 640;                    // [2][128]
    float* b2s = b1s + 256;                    // [2][64]

    const int wm2 = wid * 16;                  // 8-way M split

    for (int f = tid; f < 640; f += 256) wds[f] = ed[row0 * TT + f];
    stage_w(W1, W2, b1, b2, 0, 0, W1s, W2s, b1s, b2s, tid);
    __syncthreads();

    // preload X a-frags once (Xs is constant through the type loop)
    const uint32_t smX = sm_u32(Xs);
    const uint32_t offXA = ((wm2 + l15) * 36 + 4 * lq) * 4;
    uint32_t xa[4][4];
#pragma unroll
    for (int kc = 0; kc < 4; kc++)
        ldsm4(xa[kc][0], xa[kc][1], xa[kc][2], xa[kc][3], smX + offXA + kc * 32);

    float Y[8][4];
#pragma unroll
    for (int ni = 0; ni < 8; ni++)
#pragma unroll
        for (int jj = 0; jj < 4; jj++) Y[ni][jj] = 0.f;

    // ================= phase 2: 5-type MLP mixture ===========================
    for (int et = 0; et < TT; et++) {
        const int pb = et & 1;
        if (et + 1 < TT)
            stage_w(W1, W2, b1, b2, et + 1, pb ^ 1, W1s, W2s, b1s, b2s, tid);

        const uint32_t* W1c = W1s + pb * W1_PW;
        const uint32_t* W2c = W2s + pb * W2_PW;

        float acc2[8][4];
#pragma unroll
        for (int ni = 0; ni < 8; ni++)
#pragma unroll
            for (int jj = 0; jj < 4; jj++) acc2[ni][jj] = 0.f;

        // 8 slices of the hidden dim: each = n16 of GEMM1 = k16 of GEMM2
#pragma unroll
        for (int s = 0; s < 8; s++) {
            float h0a[4] = {0.f, 0.f, 0.f, 0.f};
            float h1a[4] = {0.f, 0.f, 0.f, 0.f};
#pragma unroll
            for (int kc = 0; kc < 4; kc++) {
                uint32_t b00 = W1c[(8 * kc + t) * 136 + 16 * s + g];
                uint32_t b01 = W1c[(8 * kc + t + 4) * 136 + 16 * s + g];
                uint32_t b10 = W1c[(8 * kc + t) * 136 + 16 * s + 8 + g];
                uint32_t b11 = W1c[(8 * kc + t + 4) * 136 + 16 * s + 8 + g];
                mma16(h0a, xa[kc][0], xa[kc][1], xa[kc][2], xa[kc][3], b00, b01);
                mma16(h1a, xa[kc][0], xa[kc][1], xa[kc][2], xa[kc][3], b10, b11);
            }
            // bias + relu, re-pack accumulators as GEMM2 A-fragments
            float bx0 = b1s[pb * 128 + 16 * s + 2 * t];
            float by0 = b1s[pb * 128 + 16 * s + 2 * t + 1];
            float bx1 = b1s[pb * 128 + 16 * s + 8 + 2 * t];
            float by1 = b1s[pb * 128 + 16 * s + 8 + 2 * t + 1];
            uint32_t af0 = h2(fmaxf(h0a[0] + bx0, 0.f), fmaxf(h0a[1] + by0, 0.f));
            uint32_t af1 = h2(fmaxf(h0a[2] + bx0, 0.f), fmaxf(h0a[3] + by0, 0.f));
            uint32_t af2 = h2(fmaxf(h1a[0] + bx1, 0.f), fmaxf(h1a[1] + by1, 0.f));
            uint32_t af3 = h2(fmaxf(h1a[2] + bx1, 0.f), fmaxf(h1a[3] + by1, 0.f));
#pragma unroll
            for (int ni = 0; ni < 8; ni++) {
                uint32_t b0 = W2c[(8 * s + t) * 72 + 8 * ni + g];
                uint32_t b1v = W2c[(8 * s + t + 4) * 72 + 8 * ni + g];
                mma16(acc2[ni], af0, af1, af2, af3, b0, b1v);
            }
        }
        // mixture accumulate
        float wA = wds[(wm2 + g) * TT + et];
        float wB = wds[(wm2 + 8 + g) * TT + et];
#pragma unroll
        for (int ni = 0; ni < 8; ni++) {
            int c = 8 * ni + 2 * t;
            float bx = b2s[pb * 64 + c], by = b2s[pb * 64 + c + 1];
            Y[ni][0] += wA * (acc2[ni][0] + bx);
            Y[ni][1] += wA * (acc2[ni][1] + by);
            Y[ni][2] += wB * (acc2[ni][2] + bx);
            Y[ni][3] += wB * (acc2[ni][3] + by);
        }
        __syncthreads();   // reads of parity pb done; et+2 staging may overwrite
    }

    // epilogue -> g_efh
    {
        int r1 = (int)row0 + wm2 + g, r2 = r1 + 8;
#pragma unroll
        for (int ni = 0; ni < 8; ni++) {
            g_efh[(size_t)r1 * 32 + 4 * ni + t] = h2(Y[ni][0], Y[ni][1]);
            g_efh[(size_t)r2 * 32 + 4 * ni + t] = h2(Y[ni][2], Y[ni][3]);
        }
    }
}

// ---------------------------------------------------------------------------
// K3: node_agg = H^T @ ef + concat ori (exact round-5/7 version: 37.6 us)
// ---------------------------------------------------------------------------
#define K3_HW 72
#define K3_BW 72
#define K3_HSZ (16 * K3_HW)
#define K3_BSZ (16 * K3_BW)
#define K3_BUF (K3_HSZ + K3_BSZ)
#define K3_SMEM_BYTES (2 * K3_BUF * 4)

__global__ __launch_bounds__(256) void k3_out(const float* __restrict__ H,
                                              const float* __restrict__ ori,
                                              float* __restrict__ out) {
    extern __shared__ uint32_t sw3[];

    const int b   = blockIdx.y;
    const int n0  = blockIdx.x * 64;
    const int tid = threadIdx.x;
    const int wid = tid >> 5, lane = tid & 31;
    const int g = lane >> 2, t = lane & 3;
    const int wm = (wid >> 1) * 16, wn = (wid & 1) * 32;

    const float* Hb = H + (size_t)b * EE * NN_;
    const uint32_t* efb = g_efh + (size_t)b * EE * 32;

    float acc[4][4];
#pragma unroll
    for (int ni = 0; ni < 4; ni++)
#pragma unroll
        for (int jj = 0; jj < 4; jj++) acc[ni][jj] = 0.f;

    const int hr = tid >> 4, hcq = tid & 15;
    const int br = tid >> 4, bcq = tid & 15;

    float4 ha0, ha1;
    uint2 eb0, eb1;
    ha0 = *(const float4*)(Hb + (size_t)(2 * hr) * NN_ + n0 + hcq * 4);
    ha1 = *(const float4*)(Hb + (size_t)(2 * hr + 1) * NN_ + n0 + hcq * 4);
    eb0 = *(const uint2*)&efb[(size_t)(2 * br) * 32 + bcq * 2];
    eb1 = *(const uint2*)&efb[(size_t)(2 * br + 1) * 32 + bcq * 2];
    {
        uint32_t* Hp = sw3; uint32_t* Bp = sw3 + K3_HSZ;
        uint4 wh;
        wh.x = h2(ha0.x, ha1.x); wh.y = h2(ha0.y, ha1.y);
        wh.z = h2(ha0.z, ha1.z); wh.w = h2(ha0.w, ha1.w);
        *(uint4*)&Hp[hr * K3_HW + hcq * 4] = wh;
        uint4 wb;
        wb.x = __byte_perm(eb0.x, eb1.x, 0x5410);
        wb.y = __byte_perm(eb0.x, eb1.x, 0x7632);
        wb.z = __byte_perm(eb0.y, eb1.y, 0x5410);
        wb.w = __byte_perm(eb0.y, eb1.y, 0x7632);
        *(uint4*)&Bp[br * K3_BW + bcq * 4] = wb;
    }
    __syncthreads();

    int buf = 0;
    for (int e0 = 0; e0 < EE; e0 += 32) {
        const int en = e0 + 32;
        if (en < EE) {
            ha0 = *(const float4*)(Hb + (size_t)(en + 2 * hr) * NN_ + n0 + hcq * 4);
            ha1 = *(const float4*)(Hb + (size_t)(en + 2 * hr + 1) * NN_ + n0 + hcq * 4);
            eb0 = *(const uint2*)&efb[(size_t)(en + 2 * br) * 32 + bcq * 2];
            eb1 = *(const uint2*)&efb[(size_t)(en + 2 * br + 1) * 32 + bcq * 2];
        }
        const uint32_t* Hp = sw3 + buf * K3_BUF;
        const uint32_t* Bp = Hp + K3_HSZ;
#pragma unroll
        for (int kk = 0; kk < 2; kk++) {
            uint32_t a[4], bf[4][2];
            a[0] = Hp[(8 * kk + t) * K3_HW + wm + g];
            a[1] = Hp[(8 * kk + t) * K3_HW + wm + 8 + g];
            a[2] = Hp[(8 * kk + t + 4) * K3_HW + wm + g];
            a[3] = Hp[(8 * kk + t + 4) * K3_HW + wm + 8 + g];
#pragma unroll
            for (int ni = 0; ni < 4; ni++) {
                bf[ni][0] = Bp[(8 * kk + t) * K3_BW + wn + 8 * ni + g];
                bf[ni][1] = Bp[(8 * kk + t + 4) * K3_BW + wn + 8 * ni + g];
            }
#pragma unroll
            for (int ni = 0; ni < 4; ni++)
                mma16(acc[ni], a[0], a[1], a[2], a[3], bf[ni][0], bf[ni][1]);
        }
        if (en < EE) {
            uint32_t* Hn = sw3 + (buf ^ 1) * K3_BUF;
            uint32_t* Bn = Hn + K3_HSZ;
            uint4 wh;
            wh.x = h2(ha0.x, ha1.x); wh.y = h2(ha0.y, ha1.y);
            wh.z = h2(ha0.z, ha1.z); wh.w = h2(ha0.w, ha1.w);
            *(uint4*)&Hn[hr * K3_HW + hcq * 4] = wh;
            uint4 wb;
            wb.x = __byte_perm(eb0.x, eb1.x, 0x5410);
            wb.y = __byte_perm(eb0.x, eb1.x, 0x7632);
            wb.z = __byte_perm(eb0.y, eb1.y, 0x5410);
            wb.w = __byte_perm(eb0.y, eb1.y, 0x7632);
            *(uint4*)&Bn[br * K3_BW + bcq * 4] = wb;
        }
        __syncthreads();
        buf ^= 1;
    }

    float*       outb = out + (size_t)b * NN_ * (2 * DD);
    const float* orib = ori + (size_t)b * NN_ * DD;
#pragma unroll
    for (int ni = 0; ni < 4; ni++) {
        int r1 = n0 + wm + g, r2 = r1 + 8;
        int c  = wn + 8 * ni + 2 * t;
        *(float2*)(outb + (size_t)r1 * (2 * DD) + c) =
            make_float2(acc[ni][0], acc[ni][1]);
        *(float2*)(outb + (size_t)r2 * (2 * DD) + c) =
            make_float2(acc[ni][2], acc[ni][3]);
    }
#pragma unroll
    for (int p = 0; p < 4; p++) {
        int f = tid + p * 256;
        int r = f >> 4, cq = f & 15;
        float4 v = *(const float4*)(orib + (size_t)(n0 + r) * DD + cq * 4);
        *(float4*)(outb + (size_t)(n0 + r) * (2 * DD) + DD + cq * 4) = v;
    }
}

// ---------------------------------------------------------------------------
extern "C" void kernel_launch(void* const* d_in, const int* in_sizes, int n_in,
                              void* d_out, int out_size) {
    const float* ed  = (const float*)d_in[0];
    const float* H   = (const float*)d_in[1];
    const float* ori = (const float*)d_in[2];
    const float* W1  = (const float*)d_in[3];
    const float* b1  = (const float*)d_in[4];
    const float* W2  = (const float*)d_in[5];
    const float* b2  = (const float*)d_in[6];
    float* out = (float*)d_out;

    cudaFuncSetAttribute(kf_fused, cudaFuncAttributeMaxDynamicSharedMemorySize,
                         KF_SMEM_BYTES);

    kf_fused<<<(BB * EE) / 128, 256, KF_SMEM_BYTES>>>(H, ori, ed, W1, b1, W2, b2);

    dim3 g3(NN_ / 64, BB);
    k3_out<<<g3, 256, K3_SMEM_BYTES>>>(H, ori, out);
}

// round 10
// speedup vs baseline: 1.1829x; 1.0267x over previous
#include <cuda_runtime.h>
#include <cuda_fp16.h>
#include <cstdint>

#define BB 64
#define EE 1024
#define NN_ 512
#define DD 64
#define HH 128
#define TT 5

// fp16-packed scratch (word = half2): edge_feature
__device__ uint32_t g_efh[BB * EE * (DD / 2)];   // 8 MB

// ---------------------------------------------------------------------------
// helpers
// ---------------------------------------------------------------------------
__device__ __forceinline__ uint32_t h2(float lo, float hi) {
    __half2 h = __floats2half2_rn(lo, hi);
    return *reinterpret_cast<uint32_t*>(&h);
}
__device__ __forceinline__ uint32_t sm_u32(const void* p) {
    return (uint32_t)__cvta_generic_to_shared(p);
}
__device__ __forceinline__ void ldsm4(uint32_t& r0, uint32_t& r1, uint32_t& r2,
                                      uint32_t& r3, uint32_t addr) {
    asm volatile("ldmatrix.sync.aligned.m8n8.x4.shared.b16 {%0,%1,%2,%3}, [%4];"
                 : "=r"(r0), "=r"(r1), "=r"(r2), "=r"(r3) : "r"(addr));
}
__device__ __forceinline__ void mma16(float* c, uint32_t a0, uint32_t a1,
                                      uint32_t a2, uint32_t a3,
                                      uint32_t b0, uint32_t b1) {
    asm volatile(
        "mma.sync.aligned.m16n8k16.row.col.f32.f16.f16.f32 "
        "{%0,%1,%2,%3}, {%4,%5,%6,%7}, {%8,%9}, {%0,%1,%2,%3};"
        : "+f"(c[0]), "+f"(c[1]), "+f"(c[2]), "+f"(c[3])
        : "r"(a0), "r"(a1), "r"(a2), "r"(a3), "r"(b0), "r"(b1));
}

// ---------------------------------------------------------------------------
// KF: fused (edges = H @ ori) + per-type MLP mixture.
// Phase 1: k-chunk 64, double-buffered; A via LDSM (stride 36), B scalar frags.
// Phase 2: round-9 proven register-relayout MLP (no Hs round trip).
// ---------------------------------------------------------------------------
#define XS_W    (128 * 36)
#define K1_AW   36
#define K1_BW   72
#define K1_ASZ  (128 * K1_AW)    // 4608 w
#define K1_BSZ  (32 * K1_BW)     // 2304 w
#define K1_BUF  (K1_ASZ + K1_BSZ)
#define W1_PW   (32 * 136)       // one parity: [32 kp(d)][136w n(h)]
#define W2_PW   (64 * 72)        // one parity: [64 kp(h)][72w n(d)]
#define K2_REGION_W (2 * W1_PW + 2 * W2_PW + 640 + 256 + 128)
#define KF_REGION_W (K2_REGION_W > 2 * K1_BUF ? K2_REGION_W : 2 * K1_BUF)
#define KF_SMEM_BYTES ((XS_W + KF_REGION_W) * 4)

__device__ __forceinline__ void stage_w(
    const float* __restrict__ W1, const float* __restrict__ W2,
    const float* __restrict__ b1, const float* __restrict__ b2,
    int tt, int par, uint32_t* W1s, uint32_t* W2s,
    float* b1s, float* b2s, int tid) {
    const float* w1 = W1 + (size_t)tt * DD * HH;
    const float* w2 = W2 + (size_t)tt * HH * DD;
#pragma unroll
    for (int p = 0; p < 4; p++) {
        int s = tid + p * 256;
        {   // W1 [64][128] -> kpair-packed [32][136w]
            int r = s >> 5, cq = s & 31;
            float4 f0 = *(const float4*)(w1 + (size_t)(2 * r) * HH + cq * 4);
            float4 f1 = *(const float4*)(w1 + (size_t)(2 * r + 1) * HH + cq * 4);
            uint4 w;
            w.x = h2(f0.x, f1.x); w.y = h2(f0.y, f1.y);
            w.z = h2(f0.z, f1.z); w.w = h2(f0.w, f1.w);
            *(uint4*)&W1s[par * W1_PW + r * 136 + cq * 4] = w;
        }
        {   // W2 [128][64] -> kpair-packed [64][72w]
            int r = s >> 4, cq = s & 15;
            float4 f0 = *(const float4*)(w2 + (size_t)(2 * r) * DD + cq * 4);
            float4 f1 = *(const float4*)(w2 + (size_t)(2 * r + 1) * DD + cq * 4);
            uint4 w;
            w.x = h2(f0.x, f1.x); w.y = h2(f0.y, f1.y);
            w.z = h2(f0.z, f1.z); w.w = h2(f0.w, f1.w);
            *(uint4*)&W2s[par * W2_PW + r * 72 + cq * 4] = w;
        }
    }
    if (tid < 128)      b1s[par * 128 + tid]        = b1[tt * HH + tid];
    else if (tid < 192) b2s[par * 64 + (tid - 128)] = b2[tt * DD + (tid - 128)];
}

__global__ __launch_bounds__(256, 2) void kf_fused(
    const float* __restrict__ H,  const float* __restrict__ ori,
    const float* __restrict__ ed, const float* __restrict__ W1,
    const float* __restrict__ b1, const float* __restrict__ W2,
    const float* __restrict__ b2) {
    extern __shared__ uint32_t smw[];
    uint32_t* Xs     = smw;          // [128][36w] persistent
    uint32_t* region = smw + XS_W;

    const int b    = blockIdx.x >> 3;
    const int m0   = (blockIdx.x & 7) * 128;
    const size_t row0 = (size_t)blockIdx.x * 128;
    const int tid  = threadIdx.x;
    const int wid  = tid >> 5, lane = tid & 31;
    const int g = lane >> 2, t = lane & 3;
    const int l15 = lane & 15, lq = lane >> 4;
    const int wm1 = (wid >> 1) * 32, wn1 = (wid & 1) * 32;   // phase-1 split

    // ================= phase 1: edges tile = H[b] tile @ ori[b], kc=64 ======
    {
        const float* Hb   = H   + (size_t)b * EE * NN_;
        const float* orib = ori + (size_t)b * NN_ * DD;

        float acc[2][4][4];
#pragma unroll
        for (int mi = 0; mi < 2; mi++)
#pragma unroll
            for (int ni = 0; ni < 4; ni++)
#pragma unroll
                for (int jj = 0; jj < 4; jj++) acc[mi][ni][jj] = 0.f;

        const int br = tid >> 4, bcq = tid & 15;   // B staging (2 kpair rows/thr)

        const uint32_t smP1 = sm_u32(region);
        const uint32_t offA = ((wm1 + l15) * K1_AW + 4 * lq) * 4;

        float4 ra[8], rb[4];
#pragma unroll
        for (int p = 0; p < 8; p++) {
            int f = tid + p * 256;
            ra[p] = *(const float4*)(Hb + (size_t)(m0 + (f >> 4)) * NN_ + (f & 15) * 4);
        }
#pragma unroll
        for (int q = 0; q < 2; q++) {
            int r = br + 16 * q;
            rb[2 * q]     = *(const float4*)(orib + (size_t)(2 * r) * DD + bcq * 4);
            rb[2 * q + 1] = *(const float4*)(orib + (size_t)(2 * r + 1) * DD + bcq * 4);
        }
        {
            uint32_t* A0 = region; uint32_t* B0 = region + K1_ASZ;
#pragma unroll
            for (int p = 0; p < 8; p++) {
                int f = tid + p * 256;
                uint2 w; w.x = h2(ra[p].x, ra[p].y); w.y = h2(ra[p].z, ra[p].w);
                *(uint2*)&A0[(f >> 4) * K1_AW + (f & 15) * 2] = w;
            }
#pragma unroll
            for (int q = 0; q < 2; q++) {
                int r = br + 16 * q;
                uint4 w;
                w.x = h2(rb[2 * q].x, rb[2 * q + 1].x);
                w.y = h2(rb[2 * q].y, rb[2 * q + 1].y);
                w.z = h2(rb[2 * q].z, rb[2 * q + 1].z);
                w.w = h2(rb[2 * q].w, rb[2 * q + 1].w);
                *(uint4*)&B0[r * K1_BW + bcq * 4] = w;
            }
        }
        __syncthreads();

        int buf = 0;
        for (int k0 = 0; k0 < NN_; k0 += 64) {
            const int kn = k0 + 64;
            if (kn < NN_) {
#pragma unroll
                for (int p = 0; p < 8; p++) {
                    int f = tid + p * 256;
                    ra[p] = *(const float4*)(Hb + (size_t)(m0 + (f >> 4)) * NN_ + kn + (f & 15) * 4);
                }
#pragma unroll
                for (int q = 0; q < 2; q++) {
                    int r = br + 16 * q;
                    rb[2 * q]     = *(const float4*)(orib + (size_t)(kn + 2 * r) * DD + bcq * 4);
                    rb[2 * q + 1] = *(const float4*)(orib + (size_t)(kn + 2 * r + 1) * DD + bcq * 4);
                }
            }
            const uint32_t abase = smP1 + (uint32_t)(buf * (K1_BUF * 4));
            const uint32_t* B_ = region + buf * K1_BUF + K1_ASZ;
#pragma unroll
            for (int kk = 0; kk < 4; kk++) {
                uint32_t a0[4], a1[4], bf[4][2];
                ldsm4(a0[0], a0[1], a0[2], a0[3], abase + offA + kk * 32);
                ldsm4(a1[0], a1[1], a1[2], a1[3], abase + offA + 2304 + kk * 32);
#pragma unroll
                for (int ni = 0; ni < 4; ni++) {
                    bf[ni][0] = B_[(8 * kk + t) * K1_BW + wn1 + 8 * ni + g];
                    bf[ni][1] = B_[(8 * kk + t + 4) * K1_BW + wn1 + 8 * ni + g];
                }
#pragma unroll
                for (int ni = 0; ni < 4; ni++) {
                    mma16(acc[0][ni], a0[0], a0[1], a0[2], a0[3], bf[ni][0], bf[ni][1]);
                    mma16(acc[1][ni], a1[0], a1[1], a1[2], a1[3], bf[ni][0], bf[ni][1]);
                }
            }
            if (kn < NN_) {
                uint32_t* An = region + (buf ^ 1) * K1_BUF;
                uint32_t* Bn = An + K1_ASZ;
#pragma unroll
                for (int p = 0; p < 8; p++) {
                    int f = tid + p * 256;
                    uint2 w; w.x = h2(ra[p].x, ra[p].y); w.y = h2(ra[p].z, ra[p].w);
                    *(uint2*)&An[(f >> 4) * K1_AW + (f & 15) * 2] = w;
                }
#pragma unroll
                for (int q = 0; q < 2; q++) {
                    int r = br + 16 * q;
                    uint4 w;
                    w.x = h2(rb[2 * q].x, rb[2 * q + 1].x);
                    w.y = h2(rb[2 * q].y, rb[2 * q + 1].y);
                    w.z = h2(rb[2 * q].z, rb[2 * q + 1].z);
                    w.w = h2(rb[2 * q].w, rb[2 * q + 1].w);
                    *(uint4*)&Bn[r * K1_BW + bcq * 4] = w;
                }
            }
            __syncthreads();
            buf ^= 1;
        }

        // epilogue: pack acc -> Xs ([e][dpair], A-layout for GEMM1)
#pragma unroll
        for (int mi = 0; mi < 2; mi++)
#pragma unroll
            for (int ni = 0; ni < 4; ni++) {
                int r1 = wm1 + 16 * mi + g, r2 = r1 + 8;
                int cw = (wn1 >> 1) + 4 * ni + t;
                Xs[r1 * 36 + cw] = h2(acc[mi][ni][0], acc[mi][ni][1]);
                Xs[r2 * 36 + cw] = h2(acc[mi][ni][2], acc[mi][ni][3]);
            }
    }
    // ================= phase 2 setup ========================================
    uint32_t* W1s = region;                    // 2 parity x [32][136w]
    uint32_t* W2s = region + 2 * W1_PW;        // 2 parity x [64][72w]
    float* wds = (float*)(W2s + 2 * W2_PW);    // [128][5]
    float* b1s = wds + 640;                    // [2][128]
    float* b2s = b1s + 256;                    // [2][64]

    const int wm2 = wid * 16;                  // 8-way M split

    for (int f = tid; f < 640; f += 256) wds[f] = ed[row0 * TT + f];
    stage_w(W1, W2, b1, b2, 0, 0, W1s, W2s, b1s, b2s, tid);
    __syncthreads();

    // preload X a-frags once (Xs is constant through the type loop)
    const uint32_t smX = sm_u32(Xs);
    const uint32_t offXA = ((wm2 + l15) * 36 + 4 * lq) * 4;
    uint32_t xa[4][4];
#pragma unroll
    for (int kc = 0; kc < 4; kc++)
        ldsm4(xa[kc][0], xa[kc][1], xa[kc][2], xa[kc][3], smX + offXA + kc * 32);

    float Y[8][4];
#pragma unroll
    for (int ni = 0; ni < 8; ni++)
#pragma unroll
        for (int jj = 0; jj < 4; jj++) Y[ni][jj] = 0.f;

    // ================= phase 2: 5-type MLP mixture ===========================
    for (int et = 0; et < TT; et++) {
        const int pb = et & 1;
        if (et + 1 < TT)
            stage_w(W1, W2, b1, b2, et + 1, pb ^ 1, W1s, W2s, b1s, b2s, tid);

        const uint32_t* W1c = W1s + pb * W1_PW;
        const uint32_t* W2c = W2s + pb * W2_PW;

        float acc2[8][4];
#pragma unroll
        for (int ni = 0; ni < 8; ni++)
#pragma unroll
            for (int jj = 0; jj < 4; jj++) acc2[ni][jj] = 0.f;

        // 8 slices of the hidden dim: each = n16 of GEMM1 = k16 of GEMM2
#pragma unroll
        for (int s = 0; s < 8; s++) {
            float h0a[4] = {0.f, 0.f, 0.f, 0.f};
            float h1a[4] = {0.f, 0.f, 0.f, 0.f};
#pragma unroll
            for (int kc = 0; kc < 4; kc++) {
                uint32_t b00 = W1c[(8 * kc + t) * 136 + 16 * s + g];
                uint32_t b01 = W1c[(8 * kc + t + 4) * 136 + 16 * s + g];
                uint32_t b10 = W1c[(8 * kc + t) * 136 + 16 * s + 8 + g];
                uint32_t b11 = W1c[(8 * kc + t + 4) * 136 + 16 * s + 8 + g];
                mma16(h0a, xa[kc][0], xa[kc][1], xa[kc][2], xa[kc][3], b00, b01);
                mma16(h1a, xa[kc][0], xa[kc][1], xa[kc][2], xa[kc][3], b10, b11);
            }
            // bias + relu, re-pack accumulators as GEMM2 A-fragments
            float bx0 = b1s[pb * 128 + 16 * s + 2 * t];
            float by0 = b1s[pb * 128 + 16 * s + 2 * t + 1];
            float bx1 = b1s[pb * 128 + 16 * s + 8 + 2 * t];
            float by1 = b1s[pb * 128 + 16 * s + 8 + 2 * t + 1];
            uint32_t af0 = h2(fmaxf(h0a[0] + bx0, 0.f), fmaxf(h0a[1] + by0, 0.f));
            uint32_t af1 = h2(fmaxf(h0a[2] + bx0, 0.f), fmaxf(h0a[3] + by0, 0.f));
            uint32_t af2 = h2(fmaxf(h1a[0] + bx1, 0.f), fmaxf(h1a[1] + by1, 0.f));
            uint32_t af3 = h2(fmaxf(h1a[2] + bx1, 0.f), fmaxf(h1a[3] + by1, 0.f));
#pragma unroll
            for (int ni = 0; ni < 8; ni++) {
                uint32_t b0 = W2c[(8 * s + t) * 72 + 8 * ni + g];
                uint32_t b1v = W2c[(8 * s + t + 4) * 72 + 8 * ni + g];
                mma16(acc2[ni], af0, af1, af2, af3, b0, b1v);
            }
        }
        // mixture accumulate
        float wA = wds[(wm2 + g) * TT + et];
        float wB = wds[(wm2 + 8 + g) * TT + et];
#pragma unroll
        for (int ni = 0; ni < 8; ni++) {
            int c = 8 * ni + 2 * t;
            float bx = b2s[pb * 64 + c], by = b2s[pb * 64 + c + 1];
            Y[ni][0] += wA * (acc2[ni][0] + bx);
            Y[ni][1] += wA * (acc2[ni][1] + by);
            Y[ni][2] += wB * (acc2[ni][2] + bx);
            Y[ni][3] += wB * (acc2[ni][3] + by);
        }
        __syncthreads();   // reads of parity pb done; et+2 staging may overwrite
    }

    // epilogue -> g_efh
    {
        int r1 = (int)row0 + wm2 + g, r2 = r1 + 8;
#pragma unroll
        for (int ni = 0; ni < 8; ni++) {
            g_efh[(size_t)r1 * 32 + 4 * ni + t] = h2(Y[ni][0], Y[ni][1]);
            g_efh[(size_t)r2 * 32 + 4 * ni + t] = h2(Y[ni][2], Y[ni][3]);
        }
    }
}

// ---------------------------------------------------------------------------
// K3: node_agg = H^T @ ef + concat ori. m-tile 64, e-chunk 64, 512 CTAs.
// Round-5 proven maps, each thread stages 2 kpair rows per operand.
// ---------------------------------------------------------------------------
#define K3_HW 72
#define K3_BW 72
#define K3_HSZ (32 * K3_HW)
#define K3_BSZ (32 * K3_BW)
#define K3_BUF (K3_HSZ + K3_BSZ)
#define K3_SMEM_BYTES (2 * K3_BUF * 4)

__global__ __launch_bounds__(256) void k3_out(const float* __restrict__ H,
                                              const float* __restrict__ ori,
                                              float* __restrict__ out) {
    extern __shared__ uint32_t sw3[];

    const int b   = blockIdx.y;
    const int n0  = blockIdx.x * 64;
    const int tid = threadIdx.x;
    const int wid = tid >> 5, lane = tid & 31;
    const int g = lane >> 2, t = lane & 3;
    const int wm = (wid >> 1) * 16, wn = (wid & 1) * 32;

    const float* Hb = H + (size_t)b * EE * NN_;
    const uint32_t* efb = g_efh + (size_t)b * EE * 32;

    float acc[4][4];
#pragma unroll
    for (int ni = 0; ni < 4; ni++)
#pragma unroll
        for (int jj = 0; jj < 4; jj++) acc[ni][jj] = 0.f;

    const int hr = tid >> 4, hcq = tid & 15;   // 2 kpair rows per thread

    float4 ha[4];
    uint2 eb[4];
#pragma unroll
    for (int q = 0; q < 2; q++) {
        int r = hr + 16 * q;
        ha[2 * q]     = *(const float4*)(Hb + (size_t)(2 * r) * NN_ + n0 + hcq * 4);
        ha[2 * q + 1] = *(const float4*)(Hb + (size_t)(2 * r + 1) * NN_ + n0 + hcq * 4);
        eb[2 * q]     = *(const uint2*)&efb[(size_t)(2 * r) * 32 + hcq * 2];
        eb[2 * q + 1] = *(const uint2*)&efb[(size_t)(2 * r + 1) * 32 + hcq * 2];
    }
    {
        uint32_t* Hp = sw3; uint32_t* Bp = sw3 + K3_HSZ;
#pragma unroll
        for (int q = 0; q < 2; q++) {
            int r = hr + 16 * q;
            uint4 wh;
            wh.x = h2(ha[2 * q].x, ha[2 * q + 1].x);
            wh.y = h2(ha[2 * q].y, ha[2 * q + 1].y);
            wh.z = h2(ha[2 * q].z, ha[2 * q + 1].z);
            wh.w = h2(ha[2 * q].w, ha[2 * q + 1].w);
            *(uint4*)&Hp[r * K3_HW + hcq * 4] = wh;
            uint4 wb;
            wb.x = __byte_perm(eb[2 * q].x, eb[2 * q + 1].x, 0x5410);
            wb.y = __byte_perm(eb[2 * q].x, eb[2 * q + 1].x, 0x7632);
            wb.z = __byte_perm(eb[2 * q].y, eb[2 * q + 1].y, 0x5410);
            wb.w = __byte_perm(eb[2 * q].y, eb[2 * q + 1].y, 0x7632);
            *(uint4*)&Bp[r * K3_BW + hcq * 4] = wb;
        }
    }
    __syncthreads();

    int buf = 0;
    for (int e0 = 0; e0 < EE; e0 += 64) {
        const int en = e0 + 64;
        if (en < EE) {
#pragma unroll
            for (int q = 0; q < 2; q++) {
                int r = hr + 16 * q;
                ha[2 * q]     = *(const float4*)(Hb + (size_t)(en + 2 * r) * NN_ + n0 + hcq * 4);
                ha[2 * q + 1] = *(const float4*)(Hb + (size_t)(en + 2 * r + 1) * NN_ + n0 + hcq * 4);
                eb[2 * q]     = *(const uint2*)&efb[(size_t)(en + 2 * r) * 32 + hcq * 2];
                eb[2 * q + 1] = *(const uint2*)&efb[(size_t)(en + 2 * r + 1) * 32 + hcq * 2];
            }
        }
        const uint32_t* Hp = sw3 + buf * K3_BUF;
        const uint32_t* Bp = Hp + K3_HSZ;
#pragma unroll
        for (int kk = 0; kk < 4; kk++) {
            uint32_t a[4], bf[4][2];
            a[0] = Hp[(8 * kk + t) * K3_HW + wm + g];
            a[1] = Hp[(8 * kk + t) * K3_HW + wm + 8 + g];
            a[2] = Hp[(8 * kk + t + 4) * K3_HW + wm + g];
            a[3] = Hp[(8 * kk + t + 4) * K3_HW + wm + 8 + g];
#pragma unroll
            for (int ni = 0; ni < 4; ni++) {
                bf[ni][0] = Bp[(8 * kk + t) * K3_BW + wn + 8 * ni + g];
                bf[ni][1] = Bp[(8 * kk + t + 4) * K3_BW + wn + 8 * ni + g];
            }
#pragma unroll
            for (int ni = 0; ni < 4; ni++)
                mma16(acc[ni], a[0], a[1], a[2], a[3], bf[ni][0], bf[ni][1]);
        }
        if (en < EE) {
            uint32_t* Hn = sw3 + (buf ^ 1) * K3_BUF;
            uint32_t* Bn = Hn + K3_HSZ;
#pragma unroll
            for (int q = 0; q < 2; q++) {
                int r = hr + 16 * q;
                uint4 wh;
                wh.x = h2(ha[2 * q].x, ha[2 * q + 1].x);
                wh.y = h2(ha[2 * q].y, ha[2 * q + 1].y);
                wh.z = h2(ha[2 * q].z, ha[2 * q + 1].z);
                wh.w = h2(ha[2 * q].w, ha[2 * q + 1].w);
                *(uint4*)&Hn[r * K3_HW + hcq * 4] = wh;
                uint4 wb;
                wb.x = __byte_perm(eb[2 * q].x, eb[2 * q + 1].x, 0x5410);
                wb.y = __byte_perm(eb[2 * q].x, eb[2 * q + 1].x, 0x7632);
                wb.z = __byte_perm(eb[2 * q].y, eb[2 * q + 1].y, 0x5410);
                wb.w = __byte_perm(eb[2 * q].y, eb[2 * q + 1].y, 0x7632);
                *(uint4*)&Bn[r * K3_BW + hcq * 4] = wb;
            }
        }
        __syncthreads();
        buf ^= 1;
    }

    float*       outb = out + (size_t)b * NN_ * (2 * DD);
    const float* orib = ori + (size_t)b * NN_ * DD;
#pragma unroll
    for (int ni = 0; ni < 4; ni++) {
        int r1 = n0 + wm + g, r2 = r1 + 8;
        int c  = wn + 8 * ni + 2 * t;
        *(float2*)(outb + (size_t)r1 * (2 * DD) + c) =
            make_float2(acc[ni][0], acc[ni][1]);
        *(float2*)(outb + (size_t)r2 * (2 * DD) + c) =
            make_float2(acc[ni][2], acc[ni][3]);
    }
#pragma unroll
    for (int p = 0; p < 4; p++) {
        int f = tid + p * 256;
        int r = f >> 4, cq = f & 15;
        float4 v = *(const float4*)(orib + (size_t)(n0 + r) * DD + cq * 4);
        *(float4*)(outb + (size_t)(n0 + r) * (2 * DD) + DD + cq * 4) = v;
    }
}

// ---------------------------------------------------------------------------
extern "C" void kernel_launch(void* const* d_in, const int* in_sizes, int n_in,
                              void* d_out, int out_size) {
    const float* ed  = (const float*)d_in[0];
    const float* H   = (const float*)d_in[1];
    const float* ori = (const float*)d_in[2];
    const float* W1  = (const float*)d_in[3];
    const float* b1  = (const float*)d_in[4];
    const float* W2  = (const float*)d_in[5];
    const float* b2  = (const float*)d_in[6];
    float* out = (float*)d_out;

    cudaFuncSetAttribute(kf_fused, cudaFuncAttributeMaxDynamicSharedMemorySize,
                         KF_SMEM_BYTES);

    kf_fused<<<(BB * EE) / 128, 256, KF_SMEM_BYTES>>>(H, ori, ed, W1, b1, W2, b2);

    dim3 g3(NN_ / 64, BB);
    k3_out<<<g3, 256, K3_SMEM_BYTES>>>(H, ori, out);
}